// round 17
// baseline (speedup 1.0000x reference)
#include <cuda_runtime.h>
#include <math.h>
#include <stdint.h>

// Problem dims
#define NR   512
#define DM   512
#define NH   8
#define HE   64
#define FF   2048
#define NL   6
#define MIX3 768

// ---------------- scratch (device globals; no allocation) ----------------
__device__ __align__(16) float g_h[NR * DM];      // fp32 residual (linear)
__device__ __align__(16) float g_ht[NR * DM];     // tf32-rounded copy (GEMM A)
__device__ __align__(16) float g_attn[NR * DM];   // rounded (GEMM A only)
__device__ __align__(16) float g_ffn[NR * FF];    // rounded (GEMM A only)
__device__ __align__(16) float g_part[6 * NR * DM];
__device__ __align__(16) float g_ks[NL * NR * DM];  // phi(K) per layer (side-stream input)
__device__ __align__(16) float g_vs[NL * NR * DM];  // V per layer (side-stream input)

__device__ __forceinline__ float rtf(float x) {
    unsigned u;
    asm("cvt.rna.tf32.f32 %0, %1;" : "=r"(u) : "f"(x));
    return __uint_as_float(u);
}

// ---------------- embedding + positional concat ----------------
__global__ void embed_kernel(const int* __restrict__ x, const int* __restrict__ ip,
                             const float* __restrict__ emb, const float* __restrict__ pe) {
    int n = blockIdx.x;
    int d = threadIdx.x;
    int tok = x[n];
    int i   = ip[0];
    const float a = emb[tok * 256 + d];
    const float b = pe[i * 256 + d];
    g_h[n * DM + d]        = a;
    g_h[n * DM + 256 + d]  = b;
    g_ht[n * DM + d]       = rtf(a);
    g_ht[n * DM + 256 + d] = rtf(b);
}

// ---------------- TF32 tensor-core GEMM core (cp.async pipelined, R11) -----
template <int ACT>   // 0 = none (+bias if non-null), 2 = bias+relu+round
__device__ __forceinline__ void gemm_body(
    const float* __restrict__ A, const float* __restrict__ B,
    const float* __restrict__ bias, float* __restrict__ C,
    int N, int K, int kStart, int kEnd, int m0, int n0)
{
    __shared__ __align__(16) float As[3][2048];
    __shared__ __align__(16) float Bs[2][2048];

    const int t    = threadIdx.x;
    const int warp = t >> 5;
    const int lane = t & 31;
    const int g    = lane >> 2;
    const int tg   = lane & 3;
    const int wm   = warp >> 2;       // 0..1 -> m offset 32*wm
    const int wn   = warp & 3;        // 0..3 -> n offset 16*wn

    const int ar  = t >> 2;           // 0..63  A row
    const int ak4 = (t & 3) * 4;      // 0,4,8,12
    const int bk  = t >> 4;           // 0..15  B k row
    const int bn4 = (t & 15) * 4;

    const int nt = (kEnd - kStart) >> 5;   // BK = 32

    const float* Ag = A + (size_t)(m0 + ar) * K + kStart;
    const float* Bg = B + (size_t)(kStart + bk) * N + n0 + bn4;

    const int aw0 = ar * 32 + (ak4 ^ ((ar & 7) << 2));
    const int aw1 = ar * 32 + ((ak4 + 16) ^ ((ar & 7) << 2));
    const uint32_t aS0 = (uint32_t)__cvta_generic_to_shared(&As[0][aw0]);
    const uint32_t aS1 = (uint32_t)__cvta_generic_to_shared(&As[0][aw1]);
    const int bw0 = bk * 64 + (bn4 ^ ((((bk << 1) + (bn4 >> 5)) & 7) << 2));
    const int bw1 = bw0 + 1024;

#define LOAD_A(kt, st) do {                                                        \
    const float* _s = Ag + (kt) * 32;                                              \
    asm volatile("cp.async.cg.shared.global [%0], [%1], 16;"                       \
                 :: "r"(aS0 + (uint32_t)(st) * 8192u), "l"(_s + ak4));             \
    asm volatile("cp.async.cg.shared.global [%0], [%1], 16;"                       \
                 :: "r"(aS1 + (uint32_t)(st) * 8192u), "l"(_s + ak4 + 16));        \
} while (0)
#define CP_COMMIT() asm volatile("cp.async.commit_group;")
#define LDG_B(kt, r0, r1) do {                                                     \
    const float* _s = Bg + (size_t)(kt) * 32 * N;                                  \
    r0 = *(const float4*)_s;                                                       \
    r1 = *(const float4*)(_s + (size_t)16 * N);                                    \
} while (0)
#define STS_B(buf, r0, r1) do {                                                    \
    float4 _q0 = make_float4(rtf((r0).x), rtf((r0).y), rtf((r0).z), rtf((r0).w));  \
    float4 _q1 = make_float4(rtf((r1).x), rtf((r1).y), rtf((r1).z), rtf((r1).w));  \
    *(float4*)&Bs[buf][bw0] = _q0;                                                 \
    *(float4*)&Bs[buf][bw1] = _q1;                                                 \
} while (0)

    float c[2][2][4];
#pragma unroll
    for (int i = 0; i < 2; i++)
#pragma unroll
        for (int j = 0; j < 2; j++)
#pragma unroll
            for (int r = 0; r < 4; r++) c[i][j][r] = 0.f;

    // prologue
    float4 b0, b1, p0, p1;
    LDG_B(0, b0, b1);
    STS_B(0, b0, b1);
    if (nt > 1) LDG_B(1, b0, b1);
    LOAD_A(0, 0);
    CP_COMMIT();
    if (nt > 1) LOAD_A(1, 1);
    CP_COMMIT();

    for (int kt = 0; kt < nt; kt++) {
        asm volatile("cp.async.wait_group 1;");
        __syncthreads();

        if (kt + 2 < nt) LOAD_A(kt + 2, (kt + 2) % 3);
        CP_COMMIT();
        if (kt + 2 < nt) LDG_B(kt + 2, p0, p1);

        const float* Ab = &As[kt % 3][0];
        const float* Bb = &Bs[kt & 1][0];

#pragma unroll
        for (int s8 = 0; s8 < 4; s8++) {
            const int kk = s8 * 8;
            unsigned a[2][4], bb[2][2];
            const int kx1 = (kk + tg) ^ (g << 2);
            const int kx2 = (kk + tg + 4) ^ (g << 2);
#pragma unroll
            for (int mt = 0; mt < 2; mt++) {
                const int r0 = (wm * 32 + mt * 16 + g) * 32;
                a[mt][0] = __float_as_uint(Ab[r0 + kx1]);
                a[mt][1] = __float_as_uint(Ab[r0 + 256 + kx1]);
                a[mt][2] = __float_as_uint(Ab[r0 + kx2]);
                a[mt][3] = __float_as_uint(Ab[r0 + 256 + kx2]);
            }
            const int k1 = kk + tg, k2 = kk + tg + 4;
#pragma unroll
            for (int ntl = 0; ntl < 2; ntl++) {
                const int col = wn * 16 + ntl * 8 + g;
                const int c5 = col >> 5;
                bb[ntl][0] = __float_as_uint(
                    Bb[k1 * 64 + (col ^ ((((k1 << 1) + c5) & 7) << 2))]);
                bb[ntl][1] = __float_as_uint(
                    Bb[k2 * 64 + (col ^ ((((k2 << 1) + c5) & 7) << 2))]);
            }
#pragma unroll
            for (int mt = 0; mt < 2; mt++)
#pragma unroll
                for (int ntl = 0; ntl < 2; ntl++) {
                    asm volatile(
                        "mma.sync.aligned.m16n8k8.row.col.f32.tf32.tf32.f32 "
                        "{%0,%1,%2,%3}, {%4,%5,%6,%7}, {%8,%9}, {%0,%1,%2,%3};"
                        : "+f"(c[mt][ntl][0]), "+f"(c[mt][ntl][1]),
                          "+f"(c[mt][ntl][2]), "+f"(c[mt][ntl][3])
                        : "r"(a[mt][0]), "r"(a[mt][1]), "r"(a[mt][2]), "r"(a[mt][3]),
                          "r"(bb[ntl][0]), "r"(bb[ntl][1]));
                }
        }

        if (kt + 1 < nt) STS_B((kt + 1) & 1, b0, b1);
        b0 = p0; b1 = p1;
    }
#undef LOAD_A
#undef CP_COMMIT
#undef LDG_B
#undef STS_B

    // epilogue: rows g/g+8, cols tg*2, tg*2+1
#pragma unroll
    for (int mt = 0; mt < 2; mt++) {
#pragma unroll
        for (int ntl = 0; ntl < 2; ntl++) {
#pragma unroll
            for (int half = 0; half < 2; half++) {
                const int row = m0 + wm * 32 + mt * 16 + g + half * 8;
                const int col = n0 + wn * 16 + ntl * 8 + tg * 2;
                float v0 = c[mt][ntl][half * 2 + 0];
                float v1 = c[mt][ntl][half * 2 + 1];
                if (bias) { v0 += bias[col]; v1 += bias[col + 1]; }
                if (ACT == 2) {
                    v0 = rtf(fmaxf(v0, 0.f));
                    v1 = rtf(fmaxf(v1, 0.f));
                }
                float2 o = make_float2(v0, v1);
                *(float2*)&C[(size_t)row * N + col] = o;
            }
        }
    }
}

// Plain GEMM (full K); tile 64x64
template <int ACT>
__global__ __launch_bounds__(256, 2) void gemm_kernel(
    const float* __restrict__ A, const float* __restrict__ B,
    const float* __restrict__ bias, float* __restrict__ C, int N, int K)
{
    gemm_body<ACT>(A, B, bias, C, N, K, 0, K, blockIdx.y * 64, blockIdx.x * 64);
}

// Split-K GEMM: partials to Cp + z*NR*N
__global__ __launch_bounds__(256, 2) void gemm_splitk_kernel(
    const float* __restrict__ A, const float* __restrict__ B,
    float* __restrict__ Cp, int N, int K, int S)
{
    const int chunk = K / S;
    const int z = blockIdx.z;
    gemm_body<0>(A, B, nullptr, Cp + (size_t)z * NR * N,
                 N, K, z * chunk, (z + 1) * chunk, blockIdx.y * 64, blockIdx.x * 64);
}

// Fused QKV with split-K 2: z = which*2 + chunk, which: 0=Q 1=K 2=V
__global__ __launch_bounds__(256, 2) void gemm_qkv_splitk_kernel(
    const float* __restrict__ Wq, const float* __restrict__ Wk, const float* __restrict__ Wv,
    float* __restrict__ part, int l)
{
    const int z = blockIdx.z;
    const int which = z >> 1;
    const int chunk = z & 1;
    const float* W = ((which == 0) ? Wq : (which == 1) ? Wk : Wv) + (size_t)l * DM * DM;
    gemm_body<0>(g_ht, W, nullptr, part + (size_t)z * NR * DM,
                 DM, DM, chunk * 256, (chunk + 1) * 256, blockIdx.y * 64, blockIdx.x * 64);
}

// ---------------- split-K reduce + bias (pred head) ----------------
__global__ void reduce_bias_kernel(const float* __restrict__ part, int P,
                                   const float* __restrict__ bias,
                                   float* __restrict__ outp, int N)
{
    const int n = blockIdx.x;
    for (int c = threadIdx.x; c < N; c += blockDim.x) {
        float v = bias[c];
        for (int p = 0; p < P; p++)
            v += part[(size_t)p * NR * N + (size_t)n * N + c];
        outp[(size_t)n * N + c] = v;
    }
}

// ---------------- attention READOUT (critical path; Si reads only) --------
// attn_m = (sum_e q_e Si[e,m] + (q.k) v_m) / (q.(Zi+k) + eps)
// Also stores phi(K) and V for the side-stream state update.
__global__ void attn_readout_kernel(const float* __restrict__ part,
                                    const float* __restrict__ bq,
                                    const float* __restrict__ bk,
                                    const float* __restrict__ bv, int l,
                                    const float* __restrict__ Si,
                                    const float* __restrict__ Zi,
                                    float* __restrict__ ks_out,
                                    float* __restrict__ vs_out)
{
    const int n = blockIdx.x;
    const int h = blockIdx.y;
    const int m = threadIdx.x;   // 0..63

    __shared__ float qs[HE], ks[HE];
    __shared__ float2 red[HE];

    const int baseqk = n * DM + h * HE;
    const size_t psz = (size_t)NR * DM;

    float qv = part[baseqk + m] + part[psz + baseqk + m] + bq[l * DM + h * HE + m];
    float kv = part[2 * psz + baseqk + m] + part[3 * psz + baseqk + m] + bk[l * DM + h * HE + m];
    const float vm = part[4 * psz + baseqk + m] + part[5 * psz + baseqk + m] + bv[l * DM + h * HE + m];

    const float q = (qv > 0.f) ? (qv + 1.f) : __expf(qv);
    const float k = (kv > 0.f) ? (kv + 1.f) : __expf(kv);
    qs[m] = q;
    ks[m] = k;
    ks_out[baseqk + m] = k;
    vs_out[baseqk + m] = vm;

    const size_t zbase = ((size_t)n * NH + h) * HE;
    red[m] = make_float2(q * (Zi[zbase + m] + k), q * k);   // den-term, qk-term
    __syncthreads();
#pragma unroll
    for (int s = 32; s > 0; s >>= 1) {
        if (m < s) {
            red[m].x += red[m + s].x;
            red[m].y += red[m + s].y;
        }
        __syncthreads();
    }
    const float den = red[0].x + 1e-6f;
    const float qk  = red[0].y;

    const size_t sbase = ((size_t)n * NH + h) * HE * HE;
    float num = 0.f;
#pragma unroll 8
    for (int e = 0; e < HE; e++)
        num = fmaf(qs[e], Si[sbase + (size_t)e * HE + m], num);

    g_attn[baseqk + m] = rtf((num + qk * vm) / den);
}

// ---------------- state update (side stream; no downstream consumer) ------
// S_out = Si + ks x vs ; Z_out = Zi + ks. 256 threads per (n,h).
__global__ void state_update_kernel(const float* __restrict__ ks_in,
                                    const float* __restrict__ vs_in,
                                    const float* __restrict__ Si,
                                    const float* __restrict__ Zi,
                                    float* __restrict__ S_out,
                                    float* __restrict__ Z_out)
{
    const int n = blockIdx.x;
    const int h = blockIdx.y;
    const int t = threadIdx.x;          // 0..255
    const int m4 = (t & 15) * 4;
    const int eg = t >> 4;              // 0..15

    __shared__ float ks[HE], vs[HE];
    const int baseqk = n * DM + h * HE;
    if (t < HE) {
        ks[t] = ks_in[baseqk + t];
        vs[t] = vs_in[baseqk + t];
    }
    __syncthreads();

    const size_t zbase = ((size_t)n * NH + h) * HE;
    if (t < HE) Z_out[zbase + t] = Zi[zbase + t] + ks[t];

    const size_t sbase = ((size_t)n * NH + h) * HE * HE;
#pragma unroll
    for (int p = 0; p < 4; p++) {
        const int e = eg + p * 16;
        const float kе = ks[e];
        const size_t off = sbase + (size_t)e * HE + m4;
        float4 si = *(const float4*)(Si + off);
        si.x += kе * vs[m4 + 0];
        si.y += kе * vs[m4 + 1];
        si.z += kе * vs[m4 + 2];
        si.w += kе * vs[m4 + 3];
        *(float4*)(S_out + off) = si;
    }
}

// ---------------- residual + split-K reduce + bias + LayerNorm -----------
__global__ void add_ln_kernel(const float* __restrict__ part,
                              int P, const float* __restrict__ bias,
                              const float* __restrict__ g, const float* __restrict__ b)
{
    const int n = blockIdx.x;
    const int t = threadIdx.x;
    __shared__ float red[256];
    __shared__ float s_mean, s_rstd;

    float v0 = g_h[n * DM + t];
    float v1 = g_h[n * DM + 256 + t];
    for (int p = 0; p < P; p++) {
        v0 += part[(size_t)p * NR * DM + n * DM + t];
        v1 += part[(size_t)p * NR * DM + n * DM + 256 + t];
    }
    if (bias) { v0 += bias[t]; v1 += bias[256 + t]; }

    red[t] = v0 + v1;
    __syncthreads();
#pragma unroll
    for (int s = 128; s > 0; s >>= 1) {
        if (t < s) red[t] += red[t + s];
        __syncthreads();
    }
    if (t == 0) s_mean = red[0] * (1.f / DM);
    __syncthreads();
    const float mean = s_mean;

    float d0 = v0 - mean, d1 = v1 - mean;
    red[t] = d0 * d0 + d1 * d1;
    __syncthreads();
#pragma unroll
    for (int s = 128; s > 0; s >>= 1) {
        if (t < s) red[t] += red[t + s];
        __syncthreads();
    }
    if (t == 0) s_rstd = rsqrtf(red[0] * (1.f / DM) + 1e-5f);
    __syncthreads();
    const float rstd = s_rstd;

    const float o0 = d0 * rstd * g[t] + b[t];
    const float o1 = d1 * rstd * g[256 + t] + b[256 + t];
    g_h[n * DM + t]        = o0;
    g_h[n * DM + 256 + t]  = o1;
    g_ht[n * DM + t]       = rtf(o0);
    g_ht[n * DM + 256 + t] = rtf(o1);
}

// ---------------- host-side launch ----------------
extern "C" void kernel_launch(void* const* d_in, const int* in_sizes, int n_in,
                              void* d_out, int out_size)
{
    const int*   x      = (const int*)  d_in[0];
    const int*   ip     = (const int*)  d_in[1];
    const float* emb    = (const float*)d_in[2];
    const float* pe     = (const float*)d_in[3];
    const float* Wq     = (const float*)d_in[4];
    const float* bq     = (const float*)d_in[5];
    const float* Wk     = (const float*)d_in[6];
    const float* bk     = (const float*)d_in[7];
    const float* Wv     = (const float*)d_in[8];
    const float* bv     = (const float*)d_in[9];
    const float* Wo     = (const float*)d_in[10];
    const float* bo     = (const float*)d_in[11];
    const float* ln1_g  = (const float*)d_in[12];
    const float* ln1_b  = (const float*)d_in[13];
    const float* lin1_w = (const float*)d_in[14];
    const float* lin1_b = (const float*)d_in[15];
    const float* lin2_w = (const float*)d_in[16];
    const float* lin2_b = (const float*)d_in[17];
    const float* ln2_g  = (const float*)d_in[18];
    const float* ln2_b  = (const float*)d_in[19];
    const float* lnf_g  = (const float*)d_in[20];
    const float* lnf_b  = (const float*)d_in[21];
    const float* pred_w = (const float*)d_in[22];
    const float* pred_b = (const float*)d_in[23];
    const float* Si     = (const float*)d_in[24];
    const float* Zi     = (const float*)d_in[25];

    float* out = (float*)d_out;
    float* out_yhat = out;
    float* out_S    = out + (size_t)NR * MIX3;
    float* out_Z    = out_S + (size_t)NL * NR * NH * HE * HE;

    float *ht, *attn, *ffn, *part, *ksb, *vsb;
    cudaGetSymbolAddress((void**)&ht,   g_ht);
    cudaGetSymbolAddress((void**)&attn, g_attn);
    cudaGetSymbolAddress((void**)&ffn,  g_ffn);
    cudaGetSymbolAddress((void**)&part, g_part);
    cudaGetSymbolAddress((void**)&ksb,  g_ks);
    cudaGetSymbolAddress((void**)&vsb,  g_vs);

    // lazy one-time side stream + events (host-side; created outside capture
    // since the first harness call is the un-captured correctness run)
    static cudaStream_t side = nullptr;
    static cudaEvent_t evR[NL];
    static cudaEvent_t evJoin = nullptr;
    if (!side) {
        cudaStreamCreateWithFlags(&side, cudaStreamNonBlocking);
        for (int i = 0; i < NL; i++)
            cudaEventCreateWithFlags(&evR[i], cudaEventDisableTiming);
        cudaEventCreateWithFlags(&evJoin, cudaEventDisableTiming);
    }

    embed_kernel<<<NR, 256>>>(x, ip, emb, pe);

    const dim3 gQKV(DM / 64, NR / 64, 6);      // 384 blocks (3 outputs x split-K 2)
    const dim3 gWo(DM / 64, NR / 64, 4);       // 256 blocks (split-K 4)
    const dim3 gF1(FF / 64, NR / 64);          // 256 blocks
    const dim3 gF2(DM / 64, NR / 64, 4);       // 256 blocks (split-K 4, chunk 512)
    const dim3 gPred(MIX3 / 64, NR / 64, 4);   // 384 blocks (split-K 4)
    const dim3 gAttn(NR, NH);

    const size_t ssz = (size_t)NR * NH * HE * HE;
    const size_t zsz = (size_t)NR * NH * HE;
    const size_t kvsz = (size_t)NR * DM;

    for (int l = 0; l < NL; l++) {
        gemm_qkv_splitk_kernel<<<gQKV, 256>>>(Wq, Wk, Wv, part, l);

        attn_readout_kernel<<<gAttn, HE>>>(part, bq, bk, bv, l,
                                           Si + l * ssz, Zi + l * zsz,
                                           ksb + l * kvsz, vsb + l * kvsz);

        // fork: state update runs on the side stream, off the critical path
        cudaEventRecord(evR[l], 0);
        cudaStreamWaitEvent(side, evR[l], 0);
        state_update_kernel<<<gAttn, 256, 0, side>>>(
            ksb + l * kvsz, vsb + l * kvsz,
            Si + l * ssz, Zi + l * zsz,
            out_S + l * ssz, out_Z + l * zsz);

        gemm_splitk_kernel<<<gWo, 256>>>(attn, Wo + (size_t)l * DM * DM, part, DM, DM, 4);
        add_ln_kernel<<<NR, 256>>>(part, 4, bo + l * DM, ln1_g + l * DM, ln1_b + l * DM);

        gemm_kernel<2><<<gF1, 256>>>(ht, lin1_w + (size_t)l * DM * FF, lin1_b + l * FF,
                                     ffn, FF, DM);
        gemm_splitk_kernel<<<gF2, 256>>>(ffn, lin2_w + (size_t)l * FF * DM, part, DM, FF, 4);
        add_ln_kernel<<<NR, 256>>>(part, 4, lin2_b + l * DM, ln2_g + l * DM, ln2_b + l * DM);
    }

    add_ln_kernel<<<NR, 256>>>(nullptr, 0, nullptr, lnf_g, lnf_b);
    gemm_splitk_kernel<<<gPred, 256>>>(ht, pred_w, part, MIX3, DM, 4);
    reduce_bias_kernel<<<NR, 256>>>(part, 4, pred_b, out_yhat, MIX3);

    // join the side stream back into the capture stream
    cudaEventRecord(evJoin, side);
    cudaStreamWaitEvent(0, evJoin, 0);
}